// round 14
// baseline (speedup 1.0000x reference)
#include <cuda_runtime.h>
#include <cstdint>

#define D 128
#define MT 16              // rows per tile (500000 = 31250 * 16)
#define LDX 132            // smem row stride (floats); 132%32=4 -> conflict-free ldmatrix
#define NTHREADS 128       // 4 warps; warp w owns output cols [32w, 32w+32)
#define GRID 304           // 2 CTAs/SM * 152 SMs (persistent)
#define STAGES 6
#define STAGE_FLOATS (MT * LDX)             // 2112
#define STAGE_BYTES  (STAGE_FLOATS * 4)     // 8448
#define PAIR_BYTES   (2 * STAGE_BYTES)      // x tile + mask tile per stage

// Scratch for W' = W @ S, pre-rounded to tf32 (allocation-free per harness rules)
__device__ __align__(16) float g_wprime[D * D];

__device__ __forceinline__ float tf32_rna(float v) {
    uint32_t r;
    asm("cvt.rna.tf32.f32 %0, %1;" : "=r"(r) : "f"(v));
    return __uint_as_float(r);
}
__device__ __forceinline__ uint32_t smem_u32(const void* p) {
    return (uint32_t)__cvta_generic_to_shared(p);
}

// ---------------------------------------------------------------------------
// Kernel 1: W' = W @ S in exact fp32, then round once to tf32.
// Trigger at ENTRY: gcn launches + runs its cp.async prologue concurrently;
// gcn's cudaGridDependencySynchronize() still waits for our completion.
// ---------------------------------------------------------------------------
__global__ void wprime_kernel(const float* __restrict__ W, const float* __restrict__ S) {
    cudaTriggerProgrammaticLaunchCompletion();
    __shared__ float wrow[D];
    const int i = blockIdx.x;
    const int j = threadIdx.x;
    wrow[j] = W[i * D + j];
    __syncthreads();
    float acc = 0.f;
#pragma unroll
    for (int k = 0; k < D; ++k) acc = fmaf(wrow[k], S[k * D + j], acc);
    g_wprime[i * D + j] = tf32_rna(acc);
}

// ---------------------------------------------------------------------------
// Kernel 2: out = relu((x .* mask) @ W')
// 6-stage cp.async pipeline (de-interleaved x/mask request streams);
// dropout multiply on ldmatrix fragments; W' register-resident per warp.
// cudaGridDependencySynchronize() is a no-op when launched without PDL.
// ---------------------------------------------------------------------------
__global__ __launch_bounds__(NTHREADS, 2) void gcn_kernel(
    const float* __restrict__ x, const float* __restrict__ mask,
    float* __restrict__ out, int nrows, int ntiles)
{
    extern __shared__ float smem[];   // STAGES * PAIR_BYTES
    const uint32_t sbase = smem_u32(smem);

    const int tid  = threadIdx.x;
    const int wid  = tid >> 5;
    const int lane = tid & 31;
    const int g    = lane >> 2;  // 0..7
    const int tg   = lane & 3;   // 0..3

    // ---- cp.async: 4 x-chunks then 4 mask-chunks (longer same-region runs) ----
    auto issue_stage = [&](int tile, int s) {
        const uint32_t xdst = sbase + (uint32_t)s * PAIR_BYTES;
        const uint32_t mdst = xdst + STAGE_BYTES;
#pragma unroll
        for (int i = 0; i < 4; ++i) {
            const int e   = tid + i * NTHREADS;      // 0..511 = 16 rows x 32 chunks
            const int row = e >> 5, c4 = e & 31;
            int r = tile * MT + row;
            const int sz = (tile < ntiles && r < nrows) ? 16 : 0;  // zero-fill OOB
            if (r >= nrows) r = 0;
            const uint32_t doff = (uint32_t)((row * LDX + c4 * 4) * 4);
            asm volatile("cp.async.cg.shared.global [%0], [%1], 16, %2;"
                         :: "r"(xdst + doff), "l"(x + (size_t)r * D + c4 * 4), "r"(sz));
        }
#pragma unroll
        for (int i = 0; i < 4; ++i) {
            const int e   = tid + i * NTHREADS;
            const int row = e >> 5, c4 = e & 31;
            int r = tile * MT + row;
            const int sz = (tile < ntiles && r < nrows) ? 16 : 0;
            if (r >= nrows) r = 0;
            const uint32_t doff = (uint32_t)((row * LDX + c4 * 4) * 4);
            asm volatile("cp.async.cg.shared.global [%0], [%1], 16, %2;"
                         :: "r"(mdst + doff), "l"(mask + (size_t)r * D + c4 * 4), "r"(sz));
        }
        asm volatile("cp.async.commit_group;");
    };

    // ---- Prologue: 5 stages in flight (overlaps wprime via PDL) ----
#pragma unroll
    for (int s = 0; s < STAGES - 1; ++s)
        issue_stage(blockIdx.x + s * GRID, s);

    // ---- Wait for wprime completion (memory visible), then preload B ----
    cudaGridDependencySynchronize();

    // tf32 m16n8k8 B (col-major 8x8 block): b0 = B[tg][n], b1 = B[tg+4][n]
    uint32_t breg[16][4][2];
#pragma unroll
    for (int kb = 0; kb < 16; ++kb)
#pragma unroll
        for (int nb = 0; nb < 4; ++nb) {
            const int col = wid * 32 + nb * 8 + g;
            breg[kb][nb][0] = __float_as_uint(g_wprime[(kb * 8 + tg    ) * D + col]);
            breg[kb][nb][1] = __float_as_uint(g_wprime[(kb * 8 + tg + 4) * D + col]);
        }

    // ---- ldmatrix per-lane offset ----
    const int lrow  = (lane & 7) + ((lane >> 3) & 1) * 8;
    const int lcoff = (lane >> 4) * 4;
    const uint32_t laneoff = (uint32_t)((lrow * LDX + lcoff) * 4);

    int p = 0;
    for (int t = blockIdx.x; t < ntiles; t += GRID) {
        asm volatile("cp.async.wait_group %0;" :: "n"(STAGES - 2));
        __syncthreads();   // stage p visible; prev compute done -> slot reusable

        // Refill the slot consumed last iteration
        issue_stage(t + (STAGES - 1) * GRID, (p + STAGES - 1) % STAGES);

        // ---- Compute tile t from stage p ----
        const uint32_t ax = sbase + (uint32_t)p * PAIR_BYTES + laneoff;
        const uint32_t am = ax + STAGE_BYTES;
        float acc[4][4] = {{0.f,0.f,0.f,0.f},{0.f,0.f,0.f,0.f},
                           {0.f,0.f,0.f,0.f},{0.f,0.f,0.f,0.f}};
#pragma unroll
        for (int kb = 0; kb < 16; ++kb) {
            uint32_t x0, x1, x2, x3, m0, m1, m2, m3;
            asm volatile("ldmatrix.sync.aligned.m8n8.x4.shared.b16 {%0,%1,%2,%3}, [%4];"
                         : "=r"(x0), "=r"(x1), "=r"(x2), "=r"(x3) : "r"(ax + kb * 32));
            asm volatile("ldmatrix.sync.aligned.m8n8.x4.shared.b16 {%0,%1,%2,%3}, [%4];"
                         : "=r"(m0), "=r"(m1), "=r"(m2), "=r"(m3) : "r"(am + kb * 32));
            const uint32_t a0 = __float_as_uint(tf32_rna(__uint_as_float(x0) * __uint_as_float(m0)));
            const uint32_t a1 = __float_as_uint(tf32_rna(__uint_as_float(x1) * __uint_as_float(m1)));
            const uint32_t a2 = __float_as_uint(tf32_rna(__uint_as_float(x2) * __uint_as_float(m2)));
            const uint32_t a3 = __float_as_uint(tf32_rna(__uint_as_float(x3) * __uint_as_float(m3)));
#pragma unroll
            for (int nb = 0; nb < 4; ++nb) {
                asm volatile(
                    "mma.sync.aligned.m16n8k8.row.col.f32.tf32.tf32.f32 "
                    "{%0,%1,%2,%3}, {%4,%5,%6,%7}, {%8,%9}, {%0,%1,%2,%3};"
                    : "+f"(acc[nb][0]), "+f"(acc[nb][1]), "+f"(acc[nb][2]), "+f"(acc[nb][3])
                    : "r"(a0), "r"(a1), "r"(a2), "r"(a3),
                      "r"(breg[kb][nb][0]), "r"(breg[kb][nb][1]));
            }
        }

        // ---- Epilogue: ReLU + streaming STG.64 ----
        const int r0 = t * MT + g;
        const int r1 = r0 + 8;
#pragma unroll
        for (int nb = 0; nb < 4; ++nb) {
            const int c = wid * 32 + nb * 8 + 2 * tg;
            if (r0 < nrows) {
                float2 v; v.x = fmaxf(acc[nb][0], 0.f); v.y = fmaxf(acc[nb][1], 0.f);
                __stcs(reinterpret_cast<float2*>(out + (size_t)r0 * D + c), v);
            }
            if (r1 < nrows) {
                float2 v; v.x = fmaxf(acc[nb][2], 0.f); v.y = fmaxf(acc[nb][3], 0.f);
                __stcs(reinterpret_cast<float2*>(out + (size_t)r1 * D + c), v);
            }
        }
        p = (p + 1) % STAGES;
    }
}

// ---------------------------------------------------------------------------
// Harness entry
// ---------------------------------------------------------------------------
extern "C" void kernel_launch(void* const* d_in, const int* in_sizes, int n_in,
                              void* d_out, int out_size) {
    const float* x    = (const float*)d_in[0];   // [N, 128]
    const float* W    = (const float*)d_in[1];   // [128, 128]
    const float* S    = (const float*)d_in[2];   // [128, 128]
    const float* mask = (const float*)d_in[3];   // [N, 128]
    float* out = (float*)d_out;

    const int nrows  = in_sizes[0] / D;
    const int ntiles = (nrows + MT - 1) / MT;

    const size_t smem = (size_t)STAGES * PAIR_BYTES;   // ~99 KB
    cudaFuncSetAttribute(gcn_kernel, cudaFuncAttributeMaxDynamicSharedMemorySize, (int)smem);

    wprime_kernel<<<D, D>>>(W, S);

    // gcn with programmatic dependent launch: prologue overlaps wprime.
    cudaLaunchConfig_t cfg = {};
    cfg.gridDim = dim3(GRID, 1, 1);
    cfg.blockDim = dim3(NTHREADS, 1, 1);
    cfg.dynamicSmemBytes = smem;
    cfg.stream = 0;
    cudaLaunchAttribute attrs[1];
    attrs[0].id = cudaLaunchAttributeProgrammaticStreamSerialization;
    attrs[0].val.programmaticStreamSerializationAllowed = 1;
    cfg.attrs = attrs;
    cfg.numAttrs = 1;
    if (cudaLaunchKernelEx(&cfg, gcn_kernel, x, mask, out, nrows, ntiles) != cudaSuccess) {
        // Defensive fallback (same correctness; PDL overlap lost only).
        gcn_kernel<<<GRID, NTHREADS, smem>>>(x, mask, out, nrows, ntiles);
    }
}

// round 15
// speedup vs baseline: 1.0443x; 1.0443x over previous
#include <cuda_runtime.h>
#include <cstdint>

#define D 128
#define MT 16              // rows per tile (500000 = 31250 * 16)
#define LDX 132            // smem row stride (floats); 132%32=4 -> conflict-free ldmatrix
#define NTHREADS 128       // 4 warps; warp w owns output cols [32w, 32w+32)
#define GRID 304           // 2 CTAs/SM * 152 SMs (persistent)
#define STAGES 4
#define STAGE_FLOATS (MT * LDX)             // 2112
#define STAGE_BYTES  (STAGE_FLOATS * 4)     // 8448
#define PAIR_BYTES   (2 * STAGE_BYTES)      // x tile + mask tile per stage

// Scratch for W' = W @ S, pre-rounded to tf32 (allocation-free per harness rules)
__device__ __align__(16) float g_wprime[D * D];

__device__ __forceinline__ float tf32_rna(float v) {
    uint32_t r;
    asm("cvt.rna.tf32.f32 %0, %1;" : "=r"(r) : "f"(v));
    return __uint_as_float(r);
}
__device__ __forceinline__ uint32_t smem_u32(const void* p) {
    return (uint32_t)__cvta_generic_to_shared(p);
}

// ---------------------------------------------------------------------------
// Kernel 1: W' = W @ S in exact fp32, then round once to tf32.
// Trigger at ENTRY: gcn launches + runs its cp.async prologue concurrently;
// gcn's cudaGridDependencySynchronize() still waits for our completion.
// ---------------------------------------------------------------------------
__global__ void wprime_kernel(const float* __restrict__ W, const float* __restrict__ S) {
    cudaTriggerProgrammaticLaunchCompletion();
    __shared__ float wrow[D];
    const int i = blockIdx.x;
    const int j = threadIdx.x;
    wrow[j] = W[i * D + j];
    __syncthreads();
    float acc = 0.f;
#pragma unroll
    for (int k = 0; k < D; ++k) acc = fmaf(wrow[k], S[k * D + j], acc);
    g_wprime[i * D + j] = tf32_rna(acc);
}

// ---------------------------------------------------------------------------
// Kernel 2: out = relu((x .* mask) @ W')
// 4-stage cp.async pipeline (interleaved x/mask 16B chunks);
// dropout multiply on ldmatrix fragments; W' register-resident per warp.
// 66 KB/CTA leaves smem headroom so wprime stays co-resident during PDL.
// ---------------------------------------------------------------------------
__global__ __launch_bounds__(NTHREADS, 2) void gcn_kernel(
    const float* __restrict__ x, const float* __restrict__ mask,
    float* __restrict__ out, int nrows, int ntiles)
{
    extern __shared__ float smem[];   // STAGES * PAIR_BYTES
    const uint32_t sbase = smem_u32(smem);

    const int tid  = threadIdx.x;
    const int wid  = tid >> 5;
    const int lane = tid & 31;
    const int g    = lane >> 2;  // 0..7
    const int tg   = lane & 3;   // 0..3

    // ---- cp.async: each thread copies 4 x 16B per array per tile ----
    auto issue_stage = [&](int tile, int s) {
        const uint32_t xdst = sbase + (uint32_t)s * PAIR_BYTES;
        const uint32_t mdst = xdst + STAGE_BYTES;
#pragma unroll
        for (int i = 0; i < 4; ++i) {
            const int e   = tid + i * NTHREADS;      // 0..511 = 16 rows x 32 chunks
            const int row = e >> 5, c4 = e & 31;
            int r = tile * MT + row;
            const int sz = (tile < ntiles && r < nrows) ? 16 : 0;  // zero-fill OOB
            if (r >= nrows) r = 0;
            const uint32_t doff = (uint32_t)((row * LDX + c4 * 4) * 4);
            const float* gx = x    + (size_t)r * D + c4 * 4;
            const float* gm = mask + (size_t)r * D + c4 * 4;
            asm volatile("cp.async.cg.shared.global [%0], [%1], 16, %2;"
                         :: "r"(xdst + doff), "l"(gx), "r"(sz));
            asm volatile("cp.async.cg.shared.global [%0], [%1], 16, %2;"
                         :: "r"(mdst + doff), "l"(gm), "r"(sz));
        }
        asm volatile("cp.async.commit_group;");
    };

    // ---- Prologue: 3 stages in flight (overlaps wprime via PDL) ----
#pragma unroll
    for (int s = 0; s < STAGES - 1; ++s)
        issue_stage(blockIdx.x + s * GRID, s);

    // ---- Wait for wprime completion (memory visible), then preload B ----
    cudaGridDependencySynchronize();

    // tf32 m16n8k8 B (col-major 8x8 block): b0 = B[tg][n], b1 = B[tg+4][n]
    uint32_t breg[16][4][2];
#pragma unroll
    for (int kb = 0; kb < 16; ++kb)
#pragma unroll
        for (int nb = 0; nb < 4; ++nb) {
            const int col = wid * 32 + nb * 8 + g;
            breg[kb][nb][0] = __float_as_uint(g_wprime[(kb * 8 + tg    ) * D + col]);
            breg[kb][nb][1] = __float_as_uint(g_wprime[(kb * 8 + tg + 4) * D + col]);
        }

    // ---- ldmatrix per-lane offset ----
    const int lrow  = (lane & 7) + ((lane >> 3) & 1) * 8;
    const int lcoff = (lane >> 4) * 4;
    const uint32_t laneoff = (uint32_t)((lrow * LDX + lcoff) * 4);

    int p = 0;
    for (int t = blockIdx.x; t < ntiles; t += GRID) {
        asm volatile("cp.async.wait_group %0;" :: "n"(STAGES - 2));
        __syncthreads();   // stage p visible; prev compute done -> slot reusable

        // Refill the slot consumed last iteration
        issue_stage(t + (STAGES - 1) * GRID, (p + STAGES - 1) % STAGES);

        // ---- Compute tile t from stage p ----
        const uint32_t ax = sbase + (uint32_t)p * PAIR_BYTES + laneoff;
        const uint32_t am = ax + STAGE_BYTES;
        float acc[4][4] = {{0.f,0.f,0.f,0.f},{0.f,0.f,0.f,0.f},
                           {0.f,0.f,0.f,0.f},{0.f,0.f,0.f,0.f}};
#pragma unroll
        for (int kb = 0; kb < 16; ++kb) {
            uint32_t x0, x1, x2, x3, m0, m1, m2, m3;
            asm volatile("ldmatrix.sync.aligned.m8n8.x4.shared.b16 {%0,%1,%2,%3}, [%4];"
                         : "=r"(x0), "=r"(x1), "=r"(x2), "=r"(x3) : "r"(ax + kb * 32));
            asm volatile("ldmatrix.sync.aligned.m8n8.x4.shared.b16 {%0,%1,%2,%3}, [%4];"
                         : "=r"(m0), "=r"(m1), "=r"(m2), "=r"(m3) : "r"(am + kb * 32));
            const uint32_t a0 = __float_as_uint(tf32_rna(__uint_as_float(x0) * __uint_as_float(m0)));
            const uint32_t a1 = __float_as_uint(tf32_rna(__uint_as_float(x1) * __uint_as_float(m1)));
            const uint32_t a2 = __float_as_uint(tf32_rna(__uint_as_float(x2) * __uint_as_float(m2)));
            const uint32_t a3 = __float_as_uint(tf32_rna(__uint_as_float(x3) * __uint_as_float(m3)));
#pragma unroll
            for (int nb = 0; nb < 4; ++nb) {
                asm volatile(
                    "mma.sync.aligned.m16n8k8.row.col.f32.tf32.tf32.f32 "
                    "{%0,%1,%2,%3}, {%4,%5,%6,%7}, {%8,%9}, {%0,%1,%2,%3};"
                    : "+f"(acc[nb][0]), "+f"(acc[nb][1]), "+f"(acc[nb][2]), "+f"(acc[nb][3])
                    : "r"(a0), "r"(a1), "r"(a2), "r"(a3),
                      "r"(breg[kb][nb][0]), "r"(breg[kb][nb][1]));
            }
        }

        // ---- Epilogue: ReLU + streaming STG.64 (evict-first, spare L2) ----
        const int r0 = t * MT + g;
        const int r1 = r0 + 8;
#pragma unroll
        for (int nb = 0; nb < 4; ++nb) {
            const int c = wid * 32 + nb * 8 + 2 * tg;
            if (r0 < nrows) {
                float2 v; v.x = fmaxf(acc[nb][0], 0.f); v.y = fmaxf(acc[nb][1], 0.f);
                __stcs(reinterpret_cast<float2*>(out + (size_t)r0 * D + c), v);
            }
            if (r1 < nrows) {
                float2 v; v.x = fmaxf(acc[nb][2], 0.f); v.y = fmaxf(acc[nb][3], 0.f);
                __stcs(reinterpret_cast<float2*>(out + (size_t)r1 * D + c), v);
            }
        }
        p = (p + 1) % STAGES;
    }
}

// ---------------------------------------------------------------------------
// Harness entry
// ---------------------------------------------------------------------------
extern "C" void kernel_launch(void* const* d_in, const int* in_sizes, int n_in,
                              void* d_out, int out_size) {
    const float* x    = (const float*)d_in[0];   // [N, 128]
    const float* W    = (const float*)d_in[1];   // [128, 128]
    const float* S    = (const float*)d_in[2];   // [128, 128]
    const float* mask = (const float*)d_in[3];   // [N, 128]
    float* out = (float*)d_out;

    const int nrows  = in_sizes[0] / D;
    const int ntiles = (nrows + MT - 1) / MT;

    const size_t smem = (size_t)STAGES * PAIR_BYTES;   // 66 KB
    cudaFuncSetAttribute(gcn_kernel, cudaFuncAttributeMaxDynamicSharedMemorySize, (int)smem);

    wprime_kernel<<<D, D>>>(W, S);

    // gcn with programmatic dependent launch: prologue overlaps wprime.
    cudaLaunchConfig_t cfg = {};
    cfg.gridDim = dim3(GRID, 1, 1);
    cfg.blockDim = dim3(NTHREADS, 1, 1);
    cfg.dynamicSmemBytes = smem;
    cfg.stream = 0;
    cudaLaunchAttribute attrs[1];
    attrs[0].id = cudaLaunchAttributeProgrammaticStreamSerialization;
    attrs[0].val.programmaticStreamSerializationAllowed = 1;
    cfg.attrs = attrs;
    cfg.numAttrs = 1;
    if (cudaLaunchKernelEx(&cfg, gcn_kernel, x, mask, out, nrows, ntiles) != cudaSuccess) {
        // Defensive fallback (same correctness; PDL overlap lost only).
        gcn_kernel<<<GRID, NTHREADS, smem>>>(x, mask, out, nrows, ntiles);
    }
}

// round 17
// speedup vs baseline: 1.0453x; 1.0009x over previous
#include <cuda_runtime.h>
#include <cstdint>

#define D 128
#define MT 16              // rows per tile (500000 = 31250 * 16)
#define LDX 132            // smem row stride (floats); 132%32=4 -> conflict-free ldmatrix
#define NTHREADS 128       // 4 warps; warp w owns output cols [32w, 32w+32)
#define GRID 304           // 2 CTAs/SM * 152 SMs (persistent)
#define STAGES 4
#define STAGE_FLOATS (MT * LDX)             // 2112
#define STAGE_BYTES  (STAGE_FLOATS * 4)     // 8448
#define PAIR_BYTES   (2 * STAGE_BYTES)      // x tile + mask tile per stage

// Scratch for W' = W @ S, pre-rounded to tf32 (allocation-free per harness rules)
__device__ __align__(16) float g_wprime[D * D];

__device__ __forceinline__ float tf32_rna(float v) {
    uint32_t r;
    asm("cvt.rna.tf32.f32 %0, %1;" : "=r"(r) : "f"(v));
    return __uint_as_float(r);
}
__device__ __forceinline__ uint32_t smem_u32(const void* p) {
    return (uint32_t)__cvta_generic_to_shared(p);
}

// ---------------------------------------------------------------------------
// Kernel 1: W' = W @ S in exact fp32, then round once to tf32.
// Trigger at ENTRY: gcn launches + runs its cp.async prologue concurrently;
// gcn's cudaGridDependencySynchronize() still waits for our completion.
// ---------------------------------------------------------------------------
__global__ void wprime_kernel(const float* __restrict__ W, const float* __restrict__ S) {
    cudaTriggerProgrammaticLaunchCompletion();
    __shared__ float wrow[D];
    const int i = blockIdx.x;
    const int j = threadIdx.x;
    wrow[j] = W[i * D + j];
    __syncthreads();
    float acc = 0.f;
#pragma unroll
    for (int k = 0; k < D; ++k) acc = fmaf(wrow[k], S[k * D + j], acc);
    g_wprime[i * D + j] = tf32_rna(acc);
}

// ---------------------------------------------------------------------------
// Kernel 2: out = relu((x .* mask) @ W')
// 4-stage cp.async pipeline (interleaved x/mask 16B chunks);
// dropout multiply on ldmatrix fragments; W' register-resident per warp.
// 66 KB/CTA leaves smem headroom so wprime stays co-resident during PDL.
// ---------------------------------------------------------------------------
__global__ __launch_bounds__(NTHREADS, 2) void gcn_kernel(
    const float* __restrict__ x, const float* __restrict__ mask,
    float* __restrict__ out, int nrows, int ntiles)
{
    extern __shared__ float smem[];   // STAGES * PAIR_BYTES
    const uint32_t sbase = smem_u32(smem);

    const int tid  = threadIdx.x;
    const int wid  = tid >> 5;
    const int lane = tid & 31;
    const int g    = lane >> 2;  // 0..7
    const int tg   = lane & 3;   // 0..3

    // ---- cp.async: each thread copies 4 x 16B per array per tile ----
    auto issue_stage = [&](int tile, int s) {
        const uint32_t xdst = sbase + (uint32_t)s * PAIR_BYTES;
        const uint32_t mdst = xdst + STAGE_BYTES;
#pragma unroll
        for (int i = 0; i < 4; ++i) {
            const int e   = tid + i * NTHREADS;      // 0..511 = 16 rows x 32 chunks
            const int row = e >> 5, c4 = e & 31;
            int r = tile * MT + row;
            const int sz = (tile < ntiles && r < nrows) ? 16 : 0;  // zero-fill OOB
            if (r >= nrows) r = 0;
            const uint32_t doff = (uint32_t)((row * LDX + c4 * 4) * 4);
            const float* gx = x    + (size_t)r * D + c4 * 4;
            const float* gm = mask + (size_t)r * D + c4 * 4;
            asm volatile("cp.async.cg.shared.global [%0], [%1], 16, %2;"
                         :: "r"(xdst + doff), "l"(gx), "r"(sz));
            asm volatile("cp.async.cg.shared.global [%0], [%1], 16, %2;"
                         :: "r"(mdst + doff), "l"(gm), "r"(sz));
        }
        asm volatile("cp.async.commit_group;");
    };

    // ---- Prologue: 3 stages in flight (overlaps wprime via PDL) ----
#pragma unroll
    for (int s = 0; s < STAGES - 1; ++s)
        issue_stage(blockIdx.x + s * GRID, s);

    // ---- Wait for wprime completion (memory visible), then preload B ----
    cudaGridDependencySynchronize();

    // tf32 m16n8k8 B (col-major 8x8 block): b0 = B[tg][n], b1 = B[tg+4][n]
    uint32_t breg[16][4][2];
#pragma unroll
    for (int kb = 0; kb < 16; ++kb)
#pragma unroll
        for (int nb = 0; nb < 4; ++nb) {
            const int col = wid * 32 + nb * 8 + g;
            breg[kb][nb][0] = __float_as_uint(g_wprime[(kb * 8 + tg    ) * D + col]);
            breg[kb][nb][1] = __float_as_uint(g_wprime[(kb * 8 + tg + 4) * D + col]);
        }

    // ---- ldmatrix per-lane offset ----
    const int lrow  = (lane & 7) + ((lane >> 3) & 1) * 8;
    const int lcoff = (lane >> 4) * 4;
    const uint32_t laneoff = (uint32_t)((lrow * LDX + lcoff) * 4);

    int p = 0;
    for (int t = blockIdx.x; t < ntiles; t += GRID) {
        asm volatile("cp.async.wait_group %0;" :: "n"(STAGES - 2));
        __syncthreads();   // stage p visible; prev compute done -> slot reusable

        // Refill the slot consumed last iteration
        issue_stage(t + (STAGES - 1) * GRID, (p + STAGES - 1) % STAGES);

        // ---- Compute tile t from stage p ----
        const uint32_t ax = sbase + (uint32_t)p * PAIR_BYTES + laneoff;
        const uint32_t am = ax + STAGE_BYTES;
        float acc[4][4] = {{0.f,0.f,0.f,0.f},{0.f,0.f,0.f,0.f},
                           {0.f,0.f,0.f,0.f},{0.f,0.f,0.f,0.f}};
#pragma unroll
        for (int kb = 0; kb < 16; ++kb) {
            uint32_t x0, x1, x2, x3, m0, m1, m2, m3;
            asm volatile("ldmatrix.sync.aligned.m8n8.x4.shared.b16 {%0,%1,%2,%3}, [%4];"
                         : "=r"(x0), "=r"(x1), "=r"(x2), "=r"(x3) : "r"(ax + kb * 32));
            asm volatile("ldmatrix.sync.aligned.m8n8.x4.shared.b16 {%0,%1,%2,%3}, [%4];"
                         : "=r"(m0), "=r"(m1), "=r"(m2), "=r"(m3) : "r"(am + kb * 32));
            const uint32_t a0 = __float_as_uint(tf32_rna(__uint_as_float(x0) * __uint_as_float(m0)));
            const uint32_t a1 = __float_as_uint(tf32_rna(__uint_as_float(x1) * __uint_as_float(m1)));
            const uint32_t a2 = __float_as_uint(tf32_rna(__uint_as_float(x2) * __uint_as_float(m2)));
            const uint32_t a3 = __float_as_uint(tf32_rna(__uint_as_float(x3) * __uint_as_float(m3)));
#pragma unroll
            for (int nb = 0; nb < 4; ++nb) {
                asm volatile(
                    "mma.sync.aligned.m16n8k8.row.col.f32.tf32.tf32.f32 "
                    "{%0,%1,%2,%3}, {%4,%5,%6,%7}, {%8,%9}, {%0,%1,%2,%3};"
                    : "+f"(acc[nb][0]), "+f"(acc[nb][1]), "+f"(acc[nb][2]), "+f"(acc[nb][3])
                    : "r"(a0), "r"(a1), "r"(a2), "r"(a3),
                      "r"(breg[kb][nb][0]), "r"(breg[kb][nb][1]));
            }
        }

        // ---- Epilogue: ReLU + streaming STG.64 (evict-first, spare L2) ----
        const int r0 = t * MT + g;
        const int r1 = r0 + 8;
#pragma unroll
        for (int nb = 0; nb < 4; ++nb) {
            const int c = wid * 32 + nb * 8 + 2 * tg;
            if (r0 < nrows) {
                float2 v; v.x = fmaxf(acc[nb][0], 0.f); v.y = fmaxf(acc[nb][1], 0.f);
                __stcs(reinterpret_cast<float2*>(out + (size_t)r0 * D + c), v);
            }
            if (r1 < nrows) {
                float2 v; v.x = fmaxf(acc[nb][2], 0.f); v.y = fmaxf(acc[nb][3], 0.f);
                __stcs(reinterpret_cast<float2*>(out + (size_t)r1 * D + c), v);
            }
        }
        p = (p + 1) % STAGES;
    }
}

// ---------------------------------------------------------------------------
// Harness entry
// ---------------------------------------------------------------------------
extern "C" void kernel_launch(void* const* d_in, const int* in_sizes, int n_in,
                              void* d_out, int out_size) {
    const float* x    = (const float*)d_in[0];   // [N, 128]
    const float* W    = (const float*)d_in[1];   // [128, 128]
    const float* S    = (const float*)d_in[2];   // [128, 128]
    const float* mask = (const float*)d_in[3];   // [N, 128]
    float* out = (float*)d_out;

    const int nrows  = in_sizes[0] / D;
    const int ntiles = (nrows + MT - 1) / MT;

    const size_t smem = (size_t)STAGES * PAIR_BYTES;   // 66 KB
    cudaFuncSetAttribute(gcn_kernel, cudaFuncAttributeMaxDynamicSharedMemorySize, (int)smem);

    wprime_kernel<<<D, D>>>(W, S);

    // gcn with programmatic dependent launch: prologue overlaps wprime.
    cudaLaunchConfig_t cfg = {};
    cfg.gridDim = dim3(GRID, 1, 1);
    cfg.blockDim = dim3(NTHREADS, 1, 1);
    cfg.dynamicSmemBytes = smem;
    cfg.stream = 0;
    cudaLaunchAttribute attrs[1];
    attrs[0].id = cudaLaunchAttributeProgrammaticStreamSerialization;
    attrs[0].val.programmaticStreamSerializationAllowed = 1;
    cfg.attrs = attrs;
    cfg.numAttrs = 1;
    if (cudaLaunchKernelEx(&cfg, gcn_kernel, x, mask, out, nrows, ntiles) != cudaSuccess) {
        // Defensive fallback (same correctness; PDL overlap lost only).
        gcn_kernel<<<GRID, NTHREADS, smem>>>(x, mask, out, nrows, ntiles);
    }
}